// round 14
// baseline (speedup 1.0000x reference)
#include <cuda_runtime.h>
#include <cstdint>

constexpr int Bc = 256;   // batch
constexpr int Cc = 128;   // channels
constexpr int Hc = 1024;  // hidden
constexpr int Ic = 512;   // input features
constexpr int Oc = 128;   // output features

// K-step 32: rows of 32 data + 4 pad words (stride 36; 36 mod 32 = 4 -> same
// conflict-free fragment bank pattern as the proven stride-20 layout)
constexpr int ROWW = 36;

// k1: 128x128 tile, 3 stages
constexpr int K1_TW = 128 * ROWW;            // A or B tile words
constexpr int K1_SW = 2 * K1_TW;             // stage words
constexpr int K1_SMEM = 3 * K1_SW * 4;       // 110592 B -> 2 CTA/SM

// k2: 256x128 tile, 3 stages
constexpr int K2_AW = 256 * ROWW;
constexpr int K2_BW = 128 * ROWW;
constexpr int K2_SW = K2_AW + K2_BW;
constexpr int K2_SMEM = 3 * K2_SW * 4;       // 165888 B -> 1 CTA/SM

// hidden activations scratch, layout [c][b][h] (k2 A-rows 4KB-strided)
__device__ float g_h[(size_t)Bc * Cc * Hc];

__device__ __forceinline__ uint32_t s2u(const void* p) {
    uint32_t a;
    asm("{ .reg .u64 t; cvta.to.shared.u64 t, %1; cvt.u32.u64 %0, t; }" : "=r"(a) : "l"(p));
    return a;
}
__device__ __forceinline__ void cp16(uint32_t dst, const float* src) {
    asm volatile("cp.async.cg.shared.global [%0], [%1], 16;" :: "r"(dst), "l"(src));
}
__device__ __forceinline__ void mma8(float4& d,
                                     uint32_t a0, uint32_t a1, uint32_t a2, uint32_t a3,
                                     uint32_t b0, uint32_t b1) {
    asm volatile(
        "mma.sync.aligned.m16n8k8.row.col.f32.tf32.tf32.f32 "
        "{%0,%1,%2,%3}, {%4,%5,%6,%7}, {%8,%9}, {%0,%1,%2,%3};"
        : "+f"(d.x), "+f"(d.y), "+f"(d.z), "+f"(d.w)
        : "r"(a0), "r"(a1), "r"(a2), "r"(a3), "r"(b0), "r"(b1));
}
// fp32 bits -> tf32 round-to-nearest
__device__ __forceinline__ uint32_t rn(uint32_t u) { return u + 0x1000u; }

// compute over one K32 stage: 4 kk-blocks of 8
#define COMPUTE_K32(AFP, BFP, ACC, TN)                                           \
    _Pragma("unroll") for (int kk = 0; kk < 32; kk += 8) {                       \
        uint32_t a[4][4], b[TN][2];                                              \
        _Pragma("unroll") for (int t = 0; t < 4; t++) {                          \
            a[t][0] = rn((AFP)[(t * 16) * ROWW + kk]);                           \
            a[t][1] = rn((AFP)[(t * 16 + 8) * ROWW + kk]);                       \
            a[t][2] = rn((AFP)[(t * 16) * ROWW + kk + 4]);                       \
            a[t][3] = rn((AFP)[(t * 16 + 8) * ROWW + kk + 4]);                   \
        }                                                                        \
        _Pragma("unroll") for (int u = 0; u < (TN); u++) {                       \
            b[u][0] = rn((BFP)[(u * 8) * ROWW + kk]);                            \
            b[u][1] = rn((BFP)[(u * 8) * ROWW + kk + 4]);                        \
        }                                                                        \
        _Pragma("unroll") for (int t = 0; t < 4; t++)                            \
            _Pragma("unroll") for (int u = 0; u < (TN); u++)                     \
                mma8((ACC)[t][u], a[t][0], a[t][1], a[t][2], a[t][3],            \
                     b[u][0], b[u][1]);                                          \
    }

// ---------------------------------------------------------------------------
// Kernel 1: h = relu(X_c @ W1_c^T + b1_c) -> g_h[c][b][h]
// 128x128 tile, 256 threads, 8 warps x 64x32 warp tiles, K-step 32, 3 stages.
// Loader per stage: A row tid>>1 koff (tid&1)*16 (4x cp16); B same (4x cp16).
// ---------------------------------------------------------------------------
__global__ __launch_bounds__(256, 2)
void mlp_k1(const float* __restrict__ x, const float* __restrict__ w1,
            const float* __restrict__ b1) {
    extern __shared__ uint32_t smw[];
    const int c = blockIdx.z, m0 = blockIdx.y * 128, n0 = blockIdx.x * 128;

    const int tid = threadIdx.x, l = tid & 31, w = tid >> 5;
    const int wm = (w & 1) * 64, wn = (w >> 1) * 32;
    const int lr4 = l >> 2, lc4 = l & 3;
    const int lrow = tid >> 1, lko = (tid & 1) * 16;
    const int faoff = (wm + lr4) * ROWW + lc4;
    const int fboff = (wn + lr4) * ROWW + lc4;

    const uint32_t sbase = s2u(smw);
    const uint32_t dstA = sbase + (uint32_t)(lrow * ROWW + lko) * 4;
    const uint32_t dstB = dstA + (uint32_t)K1_TW * 4;
    const float* srcA = x  + ((size_t)(m0 + lrow) * Cc + c) * Ic + lko;
    const float* srcB = w1 + ((size_t)c * Hc + n0 + lrow) * Ic + lko;

    float4 acc[4][4];
    #pragma unroll
    for (int t = 0; t < 4; t++)
        #pragma unroll
        for (int u = 0; u < 4; u++) acc[t][u] = make_float4(0.f, 0.f, 0.f, 0.f);

#define K1_CP(S)                                                                 \
    do {                                                                         \
        const uint32_t _o = (uint32_t)(((S) % 3) * K1_SW) * 4;                   \
        cp16(dstA + _o,      srcA + (S) * 32);                                   \
        cp16(dstA + _o + 16, srcA + (S) * 32 + 4);                               \
        cp16(dstA + _o + 32, srcA + (S) * 32 + 8);                               \
        cp16(dstA + _o + 48, srcA + (S) * 32 + 12);                              \
        cp16(dstB + _o,      srcB + (S) * 32);                                   \
        cp16(dstB + _o + 16, srcB + (S) * 32 + 4);                               \
        cp16(dstB + _o + 32, srcB + (S) * 32 + 8);                               \
        cp16(dstB + _o + 48, srcB + (S) * 32 + 12);                              \
    } while (0)

    const int NIT = Ic / 32;   // 16
    K1_CP(0); asm volatile("cp.async.commit_group;" ::: "memory");
    K1_CP(1); asm volatile("cp.async.commit_group;" ::: "memory");
    for (int i = 0; i < NIT; i++) {
        const int sl = i % 3;
        asm volatile("cp.async.wait_group 1;" ::: "memory");
        __syncthreads();
        if (i + 2 < NIT) K1_CP(i + 2);
        asm volatile("cp.async.commit_group;" ::: "memory");
        const uint32_t* Afp = smw + sl * K1_SW + faoff;
        const uint32_t* Bfp = smw + sl * K1_SW + K1_TW + fboff;
        COMPUTE_K32(Afp, Bfp, acc, 4)
    }
#undef K1_CP

    #pragma unroll
    for (int t = 0; t < 4; t++) {
        const int r0 = m0 + wm + t * 16 + lr4;
        #pragma unroll
        for (int u = 0; u < 4; u++) {
            const int n = n0 + wn + u * 8 + lc4 * 2;
            const float2 bb = *(const float2*)&b1[c * Hc + n];
            float2 lo = {fmaxf(acc[t][u].x + bb.x, 0.f),
                         fmaxf(acc[t][u].y + bb.y, 0.f)};
            float2 hi = {fmaxf(acc[t][u].z + bb.x, 0.f),
                         fmaxf(acc[t][u].w + bb.y, 0.f)};
            *(float2*)&g_h[((size_t)c * Bc + r0) * Hc + n]       = lo;
            *(float2*)&g_h[((size_t)c * Bc + r0 + 8) * Hc + n]   = hi;
        }
    }
}

// ---------------------------------------------------------------------------
// Kernel 2: out[b, :, c] = h[c, b, :] @ W2_c^T + b2_c   (output (B, O, C))
// 256x128 tile, 512 threads, 16 warps x 64x32, K-step 32, 3 stages, 1 wave.
// Loader per stage: A row tid>>1 (0..255) koff (tid&1)*16 (4x cp16);
//                   B row tid>>2 (0..127) koff (tid&3)*8 (2x cp16).
// ---------------------------------------------------------------------------
__global__ __launch_bounds__(512, 1)
void mlp_k2(const float* __restrict__ w2, const float* __restrict__ b2,
            float* __restrict__ out) {
    extern __shared__ uint32_t smw[];
    const int c = blockIdx.z;

    const int tid = threadIdx.x, l = tid & 31, w = tid >> 5;
    const int wm = (w & 3) * 64, wn = (w >> 2) * 32;
    const int lr4 = l >> 2, lc4 = l & 3;
    const int arow = tid >> 1, ako = (tid & 1) * 16;
    const int brow = tid >> 2, bko = (tid & 3) * 8;
    const int faoff = (wm + lr4) * ROWW + lc4;
    const int fboff = (wn + lr4) * ROWW + lc4;

    const uint32_t sbase = s2u(smw);
    const uint32_t dstA = sbase + (uint32_t)(arow * ROWW + ako) * 4;
    const uint32_t dstB = sbase + (uint32_t)(K2_AW + brow * ROWW + bko) * 4;
    const float* srcA = g_h + ((size_t)c * Bc + arow) * Hc + ako;
    const float* srcB = w2  + ((size_t)c * Oc + brow) * Hc + bko;

    float4 acc[4][4];
    #pragma unroll
    for (int t = 0; t < 4; t++)
        #pragma unroll
        for (int u = 0; u < 4; u++) acc[t][u] = make_float4(0.f, 0.f, 0.f, 0.f);

#define K2_CP(S)                                                                 \
    do {                                                                         \
        const uint32_t _o = (uint32_t)(((S) % 3) * K2_SW) * 4;                   \
        cp16(dstA + _o,      srcA + (S) * 32);                                   \
        cp16(dstA + _o + 16, srcA + (S) * 32 + 4);                               \
        cp16(dstA + _o + 32, srcA + (S) * 32 + 8);                               \
        cp16(dstA + _o + 48, srcA + (S) * 32 + 12);                              \
        cp16(dstB + _o,      srcB + (S) * 32);                                   \
        cp16(dstB + _o + 16, srcB + (S) * 32 + 4);                               \
    } while (0)

    const int NIT = Hc / 32;   // 32
    K2_CP(0); asm volatile("cp.async.commit_group;" ::: "memory");
    K2_CP(1); asm volatile("cp.async.commit_group;" ::: "memory");
    for (int i = 0; i < NIT; i++) {
        const int sl = i % 3;
        asm volatile("cp.async.wait_group 1;" ::: "memory");
        __syncthreads();
        if (i + 2 < NIT) K2_CP(i + 2);
        asm volatile("cp.async.commit_group;" ::: "memory");
        const uint32_t* Afp = smw + sl * K2_SW + faoff;
        const uint32_t* Bfp = smw + sl * K2_SW + K2_AW + fboff;
        COMPUTE_K32(Afp, Bfp, acc, 4)
    }
#undef K2_CP

    #pragma unroll
    for (int t = 0; t < 4; t++) {
        const int r0 = wm + t * 16 + lr4;
        #pragma unroll
        for (int u = 0; u < 4; u++) {
            const int n = wn + u * 8 + lc4 * 2;
            const float2 bb = *(const float2*)&b2[c * Oc + n];
            out[((size_t)r0 * Oc + n) * Cc + c]           = acc[t][u].x + bb.x;
            out[((size_t)r0 * Oc + n + 1) * Cc + c]       = acc[t][u].y + bb.y;
            out[((size_t)(r0 + 8) * Oc + n) * Cc + c]     = acc[t][u].z + bb.x;
            out[((size_t)(r0 + 8) * Oc + n + 1) * Cc + c] = acc[t][u].w + bb.y;
        }
    }
}

extern "C" void kernel_launch(void* const* d_in, const int* in_sizes, int n_in,
                              void* d_out, int out_size) {
    const float* x  = (const float*)d_in[0];
    const float* w1 = (const float*)d_in[1];
    const float* b1 = (const float*)d_in[2];
    const float* w2 = (const float*)d_in[3];
    const float* b2 = (const float*)d_in[4];
    float* out = (float*)d_out;

    static bool attr_set = false;
    if (!attr_set) {
        cudaFuncSetAttribute(mlp_k1, cudaFuncAttributeMaxDynamicSharedMemorySize, K1_SMEM);
        cudaFuncSetAttribute(mlp_k2, cudaFuncAttributeMaxDynamicSharedMemorySize, K2_SMEM);
        attr_set = true;
    }

    dim3 grid1(Hc / 128, Bc / 128, Cc);   // (8, 2, 128) = 2048 CTAs
    dim3 grid2(1,        1,        Cc);   // (1, 1, 128) single wave
    mlp_k1<<<grid1, dim3(256), K1_SMEM>>>(x, w1, b1);
    mlp_k2<<<grid2, dim3(512), K2_SMEM>>>(w2, b2, out);
}

// round 15
// speedup vs baseline: 1.6660x; 1.6660x over previous
#include <cuda_runtime.h>
#include <cstdint>

constexpr int Bc = 256;   // batch
constexpr int Cc = 128;   // channels
constexpr int Hc = 1024;  // hidden
constexpr int Ic = 512;   // input features
constexpr int Oc = 128;   // output features

// ---- k1: 128x128 tile, Kstep16, 4 stages (proven round-6 config) ----------
constexpr int T1W   = 128 * 20;             // A or B tile words (16 data + 4 pad)
constexpr int S1W   = 2 * T1W;              // stage words
constexpr int K1_SMEM = 4 * S1W * 4;        // 81920 B -> 2 CTA/SM

// ---- k2: 256x128 tile, Kstep16, 5 stages --------------------------------
constexpr int A2W = 256 * 20;
constexpr int B2W = 128 * 20;
constexpr int S2W = A2W + B2W;              // 7680 words
constexpr int K2_SMEM = 5 * S2W * 4;        // 153600 B -> 1 CTA/SM

// hidden activations scratch, layout [c][b][h]
__device__ float g_h[(size_t)Bc * Cc * Hc];

__device__ __forceinline__ uint32_t s2u(const void* p) {
    uint32_t a;
    asm("{ .reg .u64 t; cvta.to.shared.u64 t, %1; cvt.u32.u64 %0, t; }" : "=r"(a) : "l"(p));
    return a;
}
__device__ __forceinline__ void cp16(uint32_t dst, const float* src) {
    asm volatile("cp.async.cg.shared.global [%0], [%1], 16;" :: "r"(dst), "l"(src));
}
__device__ __forceinline__ void mma8(float4& d,
                                     uint32_t a0, uint32_t a1, uint32_t a2, uint32_t a3,
                                     uint32_t b0, uint32_t b1) {
    asm volatile(
        "mma.sync.aligned.m16n8k8.row.col.f32.tf32.tf32.f32 "
        "{%0,%1,%2,%3}, {%4,%5,%6,%7}, {%8,%9}, {%0,%1,%2,%3};"
        : "+f"(d.x), "+f"(d.y), "+f"(d.z), "+f"(d.w)
        : "r"(a0), "r"(a1), "r"(a2), "r"(a3), "r"(b0), "r"(b1));
}
// fp32 bits -> tf32 round-to-nearest
__device__ __forceinline__ uint32_t rn(uint32_t u) { return u + 0x1000u; }

// compute over one K16 stage: 2 kk-blocks of 8 (64x32 warp tile)
#define COMPUTE_K16(AFP, BFP, ACC)                                              \
    _Pragma("unroll") for (int kk = 0; kk < 16; kk += 8) {                      \
        uint32_t a[4][4], b[4][2];                                              \
        _Pragma("unroll") for (int t = 0; t < 4; t++) {                         \
            a[t][0] = rn((AFP)[(t * 16) * 20 + kk]);                            \
            a[t][1] = rn((AFP)[(t * 16 + 8) * 20 + kk]);                        \
            a[t][2] = rn((AFP)[(t * 16) * 20 + kk + 4]);                        \
            a[t][3] = rn((AFP)[(t * 16 + 8) * 20 + kk + 4]);                    \
        }                                                                       \
        _Pragma("unroll") for (int u = 0; u < 4; u++) {                         \
            b[u][0] = rn((BFP)[(u * 8) * 20 + kk]);                             \
            b[u][1] = rn((BFP)[(u * 8) * 20 + kk + 4]);                         \
        }                                                                       \
        _Pragma("unroll") for (int t = 0; t < 4; t++)                           \
            _Pragma("unroll") for (int u = 0; u < 4; u++)                       \
                mma8((ACC)[t][u], a[t][0], a[t][1], a[t][2], a[t][3],           \
                     b[u][0], b[u][1]);                                         \
    }

// ---------------------------------------------------------------------------
// Kernel 1: h = relu(X_c @ W1_c^T + b1_c) -> g_h[c][b][h]
// 128x128 tile, 256 threads, 8 warps x 64x32, Kstep16, 4 stages, 2 CTA/SM.
// ---------------------------------------------------------------------------
__global__ __launch_bounds__(256, 2)
void mlp_k1(const float* __restrict__ x, const float* __restrict__ w1,
            const float* __restrict__ b1) {
    extern __shared__ uint32_t smw[];
    const int c = blockIdx.z, m0 = blockIdx.y * 128, n0 = blockIdx.x * 128;

    const int tid = threadIdx.x, l = tid & 31, w = tid >> 5;
    const int wm = (w & 1) * 64, wn = (w >> 1) * 32;
    const int lr4 = l >> 2, lc4 = l & 3;
    const int lrow = tid >> 1, lko = (tid & 1) * 8;
    const int faoff = (wm + lr4) * 20 + lc4;
    const int fboff = (wn + lr4) * 20 + lc4;

    const uint32_t sbase = s2u(smw);
    const uint32_t dstA = sbase + (uint32_t)(lrow * 20 + lko) * 4;
    const uint32_t dstB = dstA + (uint32_t)T1W * 4;
    const float* srcA = x  + ((size_t)(m0 + lrow) * Cc + c) * Ic + lko;
    const float* srcB = w1 + ((size_t)c * Hc + n0 + lrow) * Ic + lko;

    float4 acc[4][4];
    #pragma unroll
    for (int t = 0; t < 4; t++)
        #pragma unroll
        for (int u = 0; u < 4; u++) acc[t][u] = make_float4(0.f, 0.f, 0.f, 0.f);

#define K1_CP(S)                                                                \
    do {                                                                        \
        const uint32_t _o = (uint32_t)(((S) & 3) * S1W) * 4;                    \
        cp16(dstA + _o,      srcA + (S) * 16);                                  \
        cp16(dstA + _o + 16, srcA + (S) * 16 + 4);                              \
        cp16(dstB + _o,      srcB + (S) * 16);                                  \
        cp16(dstB + _o + 16, srcB + (S) * 16 + 4);                              \
    } while (0)

    const int NIT = Ic / 16;   // 32
    #pragma unroll
    for (int s = 0; s < 3; s++) {
        K1_CP(s);
        asm volatile("cp.async.commit_group;" ::: "memory");
    }
    for (int i = 0; i < NIT; i++) {
        const int sl = i & 3;
        asm volatile("cp.async.wait_group 2;" ::: "memory");
        __syncthreads();
        if (i + 3 < NIT) K1_CP(i + 3);
        asm volatile("cp.async.commit_group;" ::: "memory");
        const uint32_t* Afp = smw + sl * S1W + faoff;
        const uint32_t* Bfp = smw + sl * S1W + T1W + fboff;
        COMPUTE_K16(Afp, Bfp, acc)
    }
#undef K1_CP

    #pragma unroll
    for (int t = 0; t < 4; t++) {
        const int r0 = m0 + wm + t * 16 + lr4;
        #pragma unroll
        for (int u = 0; u < 4; u++) {
            const int n = n0 + wn + u * 8 + lc4 * 2;
            const float2 bb = *(const float2*)&b1[c * Hc + n];
            float2 lo = {fmaxf(acc[t][u].x + bb.x, 0.f),
                         fmaxf(acc[t][u].y + bb.y, 0.f)};
            float2 hi = {fmaxf(acc[t][u].z + bb.x, 0.f),
                         fmaxf(acc[t][u].w + bb.y, 0.f)};
            *(float2*)&g_h[((size_t)c * Bc + r0) * Hc + n]     = lo;
            *(float2*)&g_h[((size_t)c * Bc + r0 + 8) * Hc + n] = hi;
        }
    }
}

// ---------------------------------------------------------------------------
// Kernel 2: out[b, :, c] = h[c, b, :] @ W2_c^T + b2_c   (output (B, O, C))
// 256x128 tile, 512 threads, 16 warps x 64x32, Kstep16, 5 stages, 1 wave.
// Loader per stage (3 cp16/thread): A rows tid>>2 and (tid>>2)+128 at koff
// (tid&3)*4; B row tid>>2 at same koff.
// ---------------------------------------------------------------------------
__global__ __launch_bounds__(512, 1)
void mlp_k2(const float* __restrict__ w2, const float* __restrict__ b2,
            float* __restrict__ out) {
    extern __shared__ uint32_t smw[];
    const int c = blockIdx.z;

    const int tid = threadIdx.x, l = tid & 31, w = tid >> 5;
    const int wm = (w & 3) * 64, wn = (w >> 2) * 32;
    const int lr4 = l >> 2, lc4 = l & 3;
    const int lrow = tid >> 2, lko = (tid & 3) * 4;
    const int faoff = (wm + lr4) * 20 + lc4;
    const int fboff = (wn + lr4) * 20 + lc4;

    const uint32_t sbase = s2u(smw);
    const uint32_t dst0 = sbase + (uint32_t)(lrow * 20 + lko) * 4;
    const uint32_t dst1 = dst0 + (uint32_t)(128 * 20) * 4;
    const uint32_t dst2 = sbase + (uint32_t)(A2W + lrow * 20 + lko) * 4;
    const float* src0 = g_h + ((size_t)c * Bc + lrow) * Hc + lko;   // A rows 0-127
    const float* src1 = src0 + (size_t)128 * Hc;                    // A rows 128-255
    const float* src2 = w2 + ((size_t)c * Oc + lrow) * Hc + lko;    // B rows

    float4 acc[4][4];
    #pragma unroll
    for (int t = 0; t < 4; t++)
        #pragma unroll
        for (int u = 0; u < 4; u++) acc[t][u] = make_float4(0.f, 0.f, 0.f, 0.f);

#define K2_CP(S, SL)                                                            \
    do {                                                                        \
        const uint32_t _o = (uint32_t)((SL) * S2W) * 4;                         \
        cp16(dst0 + _o, src0 + (S) * 16);                                       \
        cp16(dst1 + _o, src1 + (S) * 16);                                       \
        cp16(dst2 + _o, src2 + (S) * 16);                                       \
    } while (0)

    const int NIT = Hc / 16;   // 64
    K2_CP(0, 0); asm volatile("cp.async.commit_group;" ::: "memory");
    K2_CP(1, 1); asm volatile("cp.async.commit_group;" ::: "memory");
    K2_CP(2, 2); asm volatile("cp.async.commit_group;" ::: "memory");
    K2_CP(3, 3); asm volatile("cp.async.commit_group;" ::: "memory");
    int sl = 0;       // stage being consumed
    int sp = 4;       // stage slot being prefetched into
    for (int i = 0; i < NIT; i++) {
        asm volatile("cp.async.wait_group 3;" ::: "memory");
        __syncthreads();
        if (i + 4 < NIT) K2_CP(i + 4, sp);
        asm volatile("cp.async.commit_group;" ::: "memory");
        const uint32_t* Afp = smw + sl * S2W + faoff;
        const uint32_t* Bfp = smw + sl * S2W + A2W + fboff;
        COMPUTE_K16(Afp, Bfp, acc)
        if (++sl == 5) sl = 0;
        if (++sp == 5) sp = 0;
    }
#undef K2_CP

    #pragma unroll
    for (int t = 0; t < 4; t++) {
        const int r0 = wm + t * 16 + lr4;
        #pragma unroll
        for (int u = 0; u < 4; u++) {
            const int n = wn + u * 8 + lc4 * 2;
            const float2 bb = *(const float2*)&b2[c * Oc + n];
            out[((size_t)r0 * Oc + n) * Cc + c]           = acc[t][u].x + bb.x;
            out[((size_t)r0 * Oc + n + 1) * Cc + c]       = acc[t][u].y + bb.y;
            out[((size_t)(r0 + 8) * Oc + n) * Cc + c]     = acc[t][u].z + bb.x;
            out[((size_t)(r0 + 8) * Oc + n + 1) * Cc + c] = acc[t][u].w + bb.y;
        }
    }
}

extern "C" void kernel_launch(void* const* d_in, const int* in_sizes, int n_in,
                              void* d_out, int out_size) {
    const float* x  = (const float*)d_in[0];
    const float* w1 = (const float*)d_in[1];
    const float* b1 = (const float*)d_in[2];
    const float* w2 = (const float*)d_in[3];
    const float* b2 = (const float*)d_in[4];
    float* out = (float*)d_out;

    static bool attr_set = false;
    if (!attr_set) {
        cudaFuncSetAttribute(mlp_k1, cudaFuncAttributeMaxDynamicSharedMemorySize, K1_SMEM);
        cudaFuncSetAttribute(mlp_k2, cudaFuncAttributeMaxDynamicSharedMemorySize, K2_SMEM);
        attr_set = true;
    }

    dim3 grid1(Hc / 128, Bc / 128, Cc);   // (8, 2, 128) = 2048 CTAs
    dim3 grid2(1,        1,        Cc);   // (1, 1, 128) single wave
    mlp_k1<<<grid1, dim3(256), K1_SMEM>>>(x, w1, b1);
    mlp_k2<<<grid2, dim3(512), K2_SMEM>>>(w2, b2, out);
}